// round 5
// baseline (speedup 1.0000x reference)
#include <cuda_runtime.h>
#include <cstdint>

#define NROWS 256
#define DDIM  768
#define KD    128
#define NK    500
#define TK    4

// output layout (float32, reference return order)
#define OC_OFF  0
#define IDX_OFF 786432
#define SC_OFF  787456
#define QP_OFF  788480

#define NEG_INF (-3.402823466e38f)

__device__ float g_q[NROWS * KD];          // queries
__device__ float g_sc[2][NROWS][NK];       // row/col scores

__device__ __forceinline__ bool better(float a, int ia, float b, int ib) {
    return (a > b) || (a == b && ia < ib);
}

__device__ __forceinline__ void insert4(float* v, int* id, float x, int ix) {
    if (!better(x, ix, v[3], id[3])) return;
    v[3] = x; id[3] = ix;
#pragma unroll
    for (int j = 3; j > 0; j--) {
        if (better(v[j], id[j], v[j - 1], id[j - 1])) {
            float tv = v[j]; v[j] = v[j - 1]; v[j - 1] = tv;
            int   ti = id[j]; id[j] = id[j - 1]; id[j - 1] = ti;
        }
    }
}

// ---------------------------------------------------------------------------
// K1: LN + Q = LN(x) @ Wq + bq
// grid (4 coltiles of 32, 32 rowtiles of 8), 256 threads
// ---------------------------------------------------------------------------
__global__ __launch_bounds__(256) void k1_ln_q(
    const float* __restrict__ regs,
    const float* __restrict__ gamma,
    const float* __restrict__ beta,
    const float* __restrict__ Wq,
    const float* __restrict__ bq)
{
    __shared__ __align__(16) float sx[8][DDIM];   // 24 KB
    __shared__ __align__(16) float sw[128][32];   // 16 KB
    __shared__ float s_mu[8], s_rs[8];

    const int t  = threadIdx.x;
    const int ct = blockIdx.x;     // 0..3
    const int rt = blockIdx.y;     // 0..31
    const int warp = t >> 5, lane = t & 31;

    // stage 8 input rows (1536 float4)
    {
        const float4* src = (const float4*)(regs + (size_t)rt * 8 * DDIM);
        float4* dst = (float4*)&sx[0][0];
#pragma unroll
        for (int k = 0; k < 6; k++) dst[t + k * 256] = src[t + k * 256];
    }
    __syncthreads();

    // LN stats: warp w handles row w
    {
        float s = 0.f;
        for (int i = lane; i < DDIM; i += 32) s += sx[warp][i];
#pragma unroll
        for (int o = 16; o; o >>= 1) s += __shfl_xor_sync(0xffffffffu, s, o);
        const float mu = s * (1.0f / DDIM);
        float q = 0.f;
        for (int i = lane; i < DDIM; i += 32) { float d = sx[warp][i] - mu; q += d * d; }
#pragma unroll
        for (int o = 16; o; o >>= 1) q += __shfl_xor_sync(0xffffffffu, q, o);
        if (lane == 0) {
            s_mu[warp] = mu;
            s_rs[warp] = rsqrtf(q * (1.0f / DDIM) + 1e-5f);
        }
    }
    __syncthreads();

    // normalize in place
    {
        const float g0 = gamma[t], g1 = gamma[t + 256], g2 = gamma[t + 512];
        const float b0 = beta[t],  b1 = beta[t + 256],  b2 = beta[t + 512];
#pragma unroll
        for (int r = 0; r < 8; r++) {
            const float mu = s_mu[r], rs = s_rs[r];
            sx[r][t      ] = (sx[r][t      ] - mu) * rs * g0 + b0;
            sx[r][t + 256] = (sx[r][t + 256] - mu) * rs * g1 + b1;
            sx[r][t + 512] = (sx[r][t + 512] - mu) * rs * g2 + b2;
        }
    }

    // GEMM: thread (rg = t/32 row, c = t%32 col), Wq staged per 128-d chunk
    const int rg = t >> 5, c = t & 31;
    float acc = 0.f;
    for (int ch = 0; ch < 6; ch++) {
        __syncthreads();
#pragma unroll
        for (int k = 0; k < 4; k++) {
            const int idx = t + k * 256;
            const int wr = idx >> 3, c4 = idx & 7;
            const float4 w = *(const float4*)&Wq[(size_t)(ch * 128 + wr) * KD + ct * 32 + c4 * 4];
            *(float4*)&sw[wr][c4 * 4] = w;
        }
        __syncthreads();
        const float4* xrow = (const float4*)&sx[rg][ch * 128];
#pragma unroll 8
        for (int d4 = 0; d4 < 32; d4++) {
            const float4 xv = xrow[d4];
            acc += xv.x * sw[d4 * 4 + 0][c];
            acc += xv.y * sw[d4 * 4 + 1][c];
            acc += xv.z * sw[d4 * 4 + 2][c];
            acc += xv.w * sw[d4 * 4 + 3][c];
        }
    }
    const int col = ct * 32 + c;
    g_q[(size_t)(rt * 8 + rg) * KD + col] = acc + bq[col];
}

// ---------------------------------------------------------------------------
// KB: merged scores (blocks 0..255) + query_projected (blocks 256..351)
// ---------------------------------------------------------------------------
__global__ __launch_bounds__(256) void kb_scores_qp(
    const float* __restrict__ row_keys,
    const float* __restrict__ col_keys,
    const float* __restrict__ Wqc,
    const float* __restrict__ bqc,
    float* __restrict__ out)
{
    __shared__ float sk[64][65];   // role A: 16.6 KB
    __shared__ float sqa[16][64];  // role A: 4 KB
    __shared__ float sqb[16][KD];  // role B: 8 KB

    const int t = threadIdx.x;
    const int b = blockIdx.x;

    if (b < 256) {
        // ---- role A: scores = q_half @ keys^T ----
        const int kt   = b & 7;          // 0..7
        const int rt   = (b >> 3) & 15;  // 0..15
        const int side = b >> 7;         // 0..1
        const float* keys = side ? col_keys : row_keys;

#pragma unroll
        for (int k = 0; k < 4; k++) {
            const int idx = t + k * 256;
            const int kl = idx >> 4, d4 = idx & 15;
            const int kg = kt * 64 + kl;
            float4 w = make_float4(0.f, 0.f, 0.f, 0.f);
            if (kg < NK) w = *(const float4*)&keys[(size_t)kg * 64 + d4 * 4];
            sk[kl][d4 * 4 + 0] = w.x; sk[kl][d4 * 4 + 1] = w.y;
            sk[kl][d4 * 4 + 2] = w.z; sk[kl][d4 * 4 + 3] = w.w;
        }
#pragma unroll
        for (int k = 0; k < 4; k++) {
            const int idx = t + k * 256;
            const int r = idx >> 6, d = idx & 63;
            sqa[r][d] = g_q[(size_t)(rt * 16 + r) * KD + side * 64 + d];
        }
        __syncthreads();

        const int g = t >> 6, key = t & 63;
        float a0 = 0.f, a1 = 0.f, a2 = 0.f, a3 = 0.f;
#pragma unroll 8
        for (int d = 0; d < 64; d++) {
            const float kv = sk[key][d];
            a0 += kv * sqa[4 * g + 0][d];
            a1 += kv * sqa[4 * g + 1][d];
            a2 += kv * sqa[4 * g + 2][d];
            a3 += kv * sqa[4 * g + 3][d];
        }
        const int kg = kt * 64 + key;
        if (kg < NK) {
            const int r0 = rt * 16 + 4 * g;
            g_sc[side][r0 + 0][kg] = a0;
            g_sc[side][r0 + 1][kg] = a1;
            g_sc[side][r0 + 2][kg] = a2;
            g_sc[side][r0 + 3][kg] = a3;
        }
    } else {
        // ---- role B: query_projected = q @ Wqc + bqc ----
        const int b2 = b - 256;          // 0..95
        const int ct = b2 % 6;           // 128-col tile
        const int rt = b2 / 6;           // 16-row tile

#pragma unroll
        for (int k = 0; k < 8; k++) {
            const int idx = t + k * 256;
            const int r = idx >> 7, d = idx & 127;
            sqb[r][d] = g_q[(size_t)(rt * 16 + r) * KD + d];
        }
        __syncthreads();

        const int ty = t >> 6;           // 0..3 -> 4-row group
        const int tx = t & 63;           // colpair
        const int col = ct * 128 + tx * 2;
        float a00 = 0.f, a01 = 0.f, a10 = 0.f, a11 = 0.f;
        float a20 = 0.f, a21 = 0.f, a30 = 0.f, a31 = 0.f;
        const int r0 = ty * 4;
#pragma unroll 16
        for (int d = 0; d < KD; d++) {
            const float2 w = *(const float2*)&Wqc[(size_t)d * DDIM + col];
            const float q0 = sqb[r0 + 0][d];
            const float q1 = sqb[r0 + 1][d];
            const float q2 = sqb[r0 + 2][d];
            const float q3 = sqb[r0 + 3][d];
            a00 += q0 * w.x; a01 += q0 * w.y;
            a10 += q1 * w.x; a11 += q1 * w.y;
            a20 += q2 * w.x; a21 += q2 * w.y;
            a30 += q3 * w.x; a31 += q3 * w.y;
        }
        const float2 bb = *(const float2*)&bqc[col];
        const int grow = rt * 16 + r0;
        float* o = out + QP_OFF + (size_t)grow * DDIM + col;
        *(float2*)(o + 0 * DDIM) = make_float2(a00 + bb.x, a01 + bb.y);
        *(float2*)(o + 1 * DDIM) = make_float2(a10 + bb.x, a11 + bb.y);
        *(float2*)(o + 2 * DDIM) = make_float2(a20 + bb.x, a21 + bb.y);
        *(float2*)(o + 3 * DDIM) = make_float2(a30 + bb.x, a31 + bb.y);
    }
}

// ---------------------------------------------------------------------------
// KC: per-row top-4 per side, combine 4x4, write idx/scores, gather concepts
// grid 256 (one row), 128 threads
// ---------------------------------------------------------------------------
__global__ __launch_bounds__(128) void kc_topk_gather(
    const float* __restrict__ concepts,
    float* __restrict__ out)
{
    __shared__ float s_tv[2][TK];
    __shared__ int   s_ti[2][TK];
    __shared__ int   s_idx[TK];

    const int row  = blockIdx.x;
    const int t    = threadIdx.x;
    const int warp = t >> 5, lane = t & 31;

    if (warp < 2) {
        const float* sc = &g_sc[warp][row][0];
        float v[TK]; int id[TK];
#pragma unroll
        for (int j = 0; j < TK; j++) { v[j] = NEG_INF; id[j] = 0x7fffffff; }
        for (int i = lane; i < NK; i += 32) insert4(v, id, sc[i], i);
#pragma unroll
        for (int off = 16; off >= 1; off >>= 1) {
            float ov[TK]; int oi[TK];
#pragma unroll
            for (int j = 0; j < TK; j++) {
                ov[j] = __shfl_down_sync(0xffffffffu, v[j], off);
                oi[j] = __shfl_down_sync(0xffffffffu, id[j], off);
            }
            if (lane < off) {
#pragma unroll
                for (int j = 0; j < TK; j++) insert4(v, id, ov[j], oi[j]);
            }
        }
        if (lane == 0) {
#pragma unroll
            for (int j = 0; j < TK; j++) { s_tv[warp][j] = v[j]; s_ti[warp][j] = id[j]; }
        }
    }
    __syncthreads();

    if (t == 0) {
        float bv[TK]; int bi[TK];
#pragma unroll
        for (int j = 0; j < TK; j++) { bv[j] = NEG_INF; bi[j] = 0x7fffffff; }
#pragma unroll
        for (int i = 0; i < TK; i++)
#pragma unroll
            for (int j = 0; j < TK; j++)
                insert4(bv, bi, s_tv[0][i] + s_tv[1][j], s_ti[0][i] * NK + s_ti[1][j]);
#pragma unroll
        for (int n = 0; n < TK; n++) {
            out[SC_OFF  + row * TK + n] = bv[n];
            out[IDX_OFF + row * TK + n] = (float)bi[n];
            s_idx[n] = bi[n];
        }
    }
    __syncthreads();

    // gather 4 concept rows (4 x 192 float4), 6 per thread
#pragma unroll
    for (int k = 0; k < 6; k++) {
        const int i = t + k * 128;
        const int n = i / 192, j = i % 192;
        const int cid = s_idx[n];
        const float4 val = ((const float4*)concepts)[(size_t)cid * 192 + j];
        ((float4*)(out + OC_OFF))[(size_t)(row * TK + n) * 192 + j] = val;
    }
}

extern "C" void kernel_launch(void* const* d_in, const int* in_sizes, int n_in,
                              void* d_out, int out_size) {
    const float* regs     = (const float*)d_in[0];
    const float* row_keys = (const float*)d_in[1];
    const float* col_keys = (const float*)d_in[2];
    const float* concepts = (const float*)d_in[3];
    const float* gamma    = (const float*)d_in[4];
    const float* beta     = (const float*)d_in[5];
    const float* Wq       = (const float*)d_in[6];
    const float* bq       = (const float*)d_in[7];
    const float* Wqc      = (const float*)d_in[8];
    const float* bqc      = (const float*)d_in[9];
    float* out = (float*)d_out;

    k1_ln_q<<<dim3(4, 32), 256>>>(regs, gamma, beta, Wq, bq);
    kb_scores_qp<<<352, 256>>>(row_keys, col_keys, Wqc, bqc, out);
    kc_topk_gather<<<256, 128>>>(concepts, out);
}

// round 6
// speedup vs baseline: 1.0721x; 1.0721x over previous
#include <cuda_runtime.h>
#include <cstdint>

#define NROWS 256
#define DDIM  768
#define KD    128
#define NK    500
#define TK    4

// output layout (float32, reference return order)
#define OC_OFF  0
#define IDX_OFF 786432
#define SC_OFF  787456
#define QP_OFF  788480

#define NEG_INF (-3.402823466e38f)

__device__ float g_q[NROWS * KD];          // queries
__device__ float g_sc[2][NROWS][NK];       // row/col scores

__device__ __forceinline__ bool better(float a, int ia, float b, int ib) {
    return (a > b) || (a == b && ia < ib);
}

__device__ __forceinline__ void insert4(float* v, int* id, float x, int ix) {
    if (!better(x, ix, v[3], id[3])) return;
    v[3] = x; id[3] = ix;
#pragma unroll
    for (int j = 3; j > 0; j--) {
        if (better(v[j], id[j], v[j - 1], id[j - 1])) {
            float tv = v[j]; v[j] = v[j - 1]; v[j - 1] = tv;
            int   ti = id[j]; id[j] = id[j - 1]; id[j - 1] = ti;
        }
    }
}

// ---------------------------------------------------------------------------
// K1: LN + Q = LN(x) @ Wq + bq
// grid (8 coltiles of 16, 32 rowtiles of 8), 256 threads
// per thread: 4 cols (float4) x 1 row x 96-deep d slice; smem reduce over 8 slices
// ---------------------------------------------------------------------------
__global__ __launch_bounds__(256) void k1_ln_q(
    const float* __restrict__ regs,
    const float* __restrict__ gamma,
    const float* __restrict__ beta,
    const float* __restrict__ Wq,
    const float* __restrict__ bq)
{
    __shared__ __align__(16) float sx[8][772];       // padded: 8-row conflict-free
    __shared__ __align__(16) float spart[8][8][16];  // [d8][row][col]
    __shared__ float s_mu[8], s_rs[8];

    const int t  = threadIdx.x;
    const int ct = blockIdx.x;     // 0..7  (16 cols)
    const int rt = blockIdx.y;     // 0..31 (8 rows)
    const int warp = t >> 5, lane = t & 31;

    // stage 8 input rows (1536 float4, row-padded dst)
    {
        const float4* src = (const float4*)(regs + (size_t)rt * 8 * DDIM);
#pragma unroll
        for (int k = 0; k < 6; k++) {
            const int idx = t + k * 256;            // 0..1535
            const int r = idx / 192, j = idx % 192;
            *(float4*)&sx[r][j * 4] = src[idx];
        }
    }
    __syncthreads();

    // LN stats: warp w handles row w
    {
        float s = 0.f;
        for (int i = lane; i < DDIM; i += 32) s += sx[warp][i];
#pragma unroll
        for (int o = 16; o; o >>= 1) s += __shfl_xor_sync(0xffffffffu, s, o);
        const float mu = s * (1.0f / DDIM);
        float q = 0.f;
        for (int i = lane; i < DDIM; i += 32) { float d = sx[warp][i] - mu; q += d * d; }
#pragma unroll
        for (int o = 16; o; o >>= 1) q += __shfl_xor_sync(0xffffffffu, q, o);
        if (lane == 0) {
            s_mu[warp] = mu;
            s_rs[warp] = rsqrtf(q * (1.0f / DDIM) + 1e-5f);
        }
    }
    __syncthreads();

    // normalize in place
    {
        const float g0 = gamma[t], g1 = gamma[t + 256], g2 = gamma[t + 512];
        const float b0 = beta[t],  b1 = beta[t + 256],  b2 = beta[t + 512];
#pragma unroll
        for (int r = 0; r < 8; r++) {
            const float mu = s_mu[r], rs = s_rs[r];
            sx[r][t      ] = (sx[r][t      ] - mu) * rs * g0 + b0;
            sx[r][t + 256] = (sx[r][t + 256] - mu) * rs * g1 + b1;
            sx[r][t + 512] = (sx[r][t + 512] - mu) * rs * g2 + b2;
        }
    }
    __syncthreads();

    // GEMM: c4 = col quad, s -> (row, d-slice of 96)
    {
        const int c4 = t & 3;
        const int s  = t >> 2;
        const int r  = s & 7;
        const int d8 = s >> 3;          // == warp
        const float* wp = Wq + (size_t)(d8 * 96) * KD + ct * 16 + c4 * 4;
        const float* xp = &sx[r][d8 * 96];
        float ax = 0.f, ay = 0.f, az = 0.f, aw = 0.f;
#pragma unroll 8
        for (int d = 0; d < 96; d++) {
            const float4 w = *(const float4*)(wp + (size_t)d * KD);
            const float xv = xp[d];
            ax += xv * w.x; ay += xv * w.y; az += xv * w.z; aw += xv * w.w;
        }
        *(float4*)&spart[d8][r][c4 * 4] = make_float4(ax, ay, az, aw);
    }
    __syncthreads();

    if (t < 128) {
        const int r = t >> 4, c = t & 15;
        float sum = bq[ct * 16 + c];
#pragma unroll
        for (int k = 0; k < 8; k++) sum += spart[k][r][c];
        g_q[(size_t)(rt * 8 + r) * KD + ct * 16 + c] = sum;
    }
}

// ---------------------------------------------------------------------------
// KB: merged scores (blocks 0..127) + query_projected (blocks 128..319)
// ---------------------------------------------------------------------------
__global__ __launch_bounds__(256) void kb_scores_qp(
    const float* __restrict__ row_keys,
    const float* __restrict__ col_keys,
    const float* __restrict__ Wqc,
    const float* __restrict__ bqc,
    float* __restrict__ out)
{
    __shared__ float sk[64][66];   // role A: keys, d-major (transposed), 16.9 KB
    __shared__ float sq[32][64];   // role A: q halves, 8 KB
    __shared__ float sqb[16][KD];  // role B: 8 KB

    const int t = threadIdx.x;
    const int b = blockIdx.x;

    if (b < 128) {
        // ---- role A: scores = q_half @ keys^T  (64 keys x 32 rows) ----
        const int kt   = b & 7;          // 0..7
        const int rt   = (b >> 3) & 7;   // 0..7 (32 rows)
        const int side = b >> 6;         // 0..1
        const float* keys = side ? col_keys : row_keys;

        // stage keys transposed: sk[d][key]
        {
            const int d  = t & 63;
            const int k0 = t >> 6;       // 0..3
#pragma unroll
            for (int k = 0; k < 16; k++) {
                const int kl = k0 + k * 4;
                const int kg = kt * 64 + kl;
                sk[d][kl] = (kg < NK) ? keys[(size_t)kg * 64 + d] : 0.f;
            }
        }
        // stage q tile (32 rows x 64 half-dims)
#pragma unroll
        for (int k = 0; k < 8; k++) {
            const int idx = t + k * 256;
            const int r = idx >> 6, d = idx & 63;
            sq[r][d] = g_q[(size_t)(rt * 32 + r) * KD + side * 64 + d];
        }
        __syncthreads();

        const int kx = t & 31;           // key pair -> keys 2kx, 2kx+1
        const int rg = t >> 5;           // rows 4rg..4rg+3
        float a0x = 0.f, a0y = 0.f, a1x = 0.f, a1y = 0.f;
        float a2x = 0.f, a2y = 0.f, a3x = 0.f, a3y = 0.f;
#pragma unroll 8
        for (int d = 0; d < 64; d++) {
            const float2 kv = *(const float2*)&sk[d][2 * kx];
            const float q0 = sq[4 * rg + 0][d];
            const float q1 = sq[4 * rg + 1][d];
            const float q2 = sq[4 * rg + 2][d];
            const float q3 = sq[4 * rg + 3][d];
            a0x += q0 * kv.x; a0y += q0 * kv.y;
            a1x += q1 * kv.x; a1y += q1 * kv.y;
            a2x += q2 * kv.x; a2y += q2 * kv.y;
            a3x += q3 * kv.x; a3y += q3 * kv.y;
        }
        const int kg0 = kt * 64 + 2 * kx;
        if (kg0 < NK) {
            const int r0 = rt * 32 + 4 * rg;
            *(float2*)&g_sc[side][r0 + 0][kg0] = make_float2(a0x, a0y);
            *(float2*)&g_sc[side][r0 + 1][kg0] = make_float2(a1x, a1y);
            *(float2*)&g_sc[side][r0 + 2][kg0] = make_float2(a2x, a2y);
            *(float2*)&g_sc[side][r0 + 3][kg0] = make_float2(a3x, a3y);
        }
    } else {
        // ---- role B: query_projected = q @ Wqc + bqc (16 rows x 64 cols) ----
        const int b2 = b - 128;          // 0..191
        const int ct = b2 % 12;          // 64-col tile
        const int rt = b2 / 12;          // 16-row tile

#pragma unroll
        for (int k = 0; k < 8; k++) {
            const int idx = t + k * 256;
            const int r = idx >> 7, d = idx & 127;
            sqb[r][d] = g_q[(size_t)(rt * 16 + r) * KD + d];
        }
        __syncthreads();

        const int tx = t & 31;           // col pair
        const int ty = t >> 5;           // 8 row pairs
        const int col = ct * 64 + tx * 2;
        const int r0 = ty * 2;
        float a00 = 0.f, a01 = 0.f, a10 = 0.f, a11 = 0.f;
#pragma unroll 16
        for (int d = 0; d < KD; d++) {
            const float2 w = *(const float2*)&Wqc[(size_t)d * DDIM + col];
            const float q0 = sqb[r0 + 0][d];
            const float q1 = sqb[r0 + 1][d];
            a00 += q0 * w.x; a01 += q0 * w.y;
            a10 += q1 * w.x; a11 += q1 * w.y;
        }
        const float2 bb = *(const float2*)&bqc[col];
        const int grow = rt * 16 + r0;
        float* o = out + QP_OFF + (size_t)grow * DDIM + col;
        *(float2*)(o + 0 * DDIM) = make_float2(a00 + bb.x, a01 + bb.y);
        *(float2*)(o + 1 * DDIM) = make_float2(a10 + bb.x, a11 + bb.y);
    }
}

// ---------------------------------------------------------------------------
// KC: per-row top-4 per side, combine 4x4, write idx/scores, gather concepts
// grid 256 (one row), 128 threads
// ---------------------------------------------------------------------------
__global__ __launch_bounds__(128) void kc_topk_gather(
    const float* __restrict__ concepts,
    float* __restrict__ out)
{
    __shared__ float s_tv[2][TK];
    __shared__ int   s_ti[2][TK];
    __shared__ int   s_idx[TK];

    const int row  = blockIdx.x;
    const int t    = threadIdx.x;
    const int warp = t >> 5, lane = t & 31;

    if (warp < 2) {
        const float* sc = &g_sc[warp][row][0];
        float v[TK]; int id[TK];
#pragma unroll
        for (int j = 0; j < TK; j++) { v[j] = NEG_INF; id[j] = 0x7fffffff; }
        for (int i = lane; i < NK; i += 32) insert4(v, id, sc[i], i);
#pragma unroll
        for (int off = 16; off >= 1; off >>= 1) {
            float ov[TK]; int oi[TK];
#pragma unroll
            for (int j = 0; j < TK; j++) {
                ov[j] = __shfl_down_sync(0xffffffffu, v[j], off);
                oi[j] = __shfl_down_sync(0xffffffffu, id[j], off);
            }
            if (lane < off) {
#pragma unroll
                for (int j = 0; j < TK; j++) insert4(v, id, ov[j], oi[j]);
            }
        }
        if (lane == 0) {
#pragma unroll
            for (int j = 0; j < TK; j++) { s_tv[warp][j] = v[j]; s_ti[warp][j] = id[j]; }
        }
    }
    __syncthreads();

    if (t == 0) {
        float bv[TK]; int bi[TK];
#pragma unroll
        for (int j = 0; j < TK; j++) { bv[j] = NEG_INF; bi[j] = 0x7fffffff; }
#pragma unroll
        for (int i = 0; i < TK; i++)
#pragma unroll
            for (int j = 0; j < TK; j++)
                insert4(bv, bi, s_tv[0][i] + s_tv[1][j], s_ti[0][i] * NK + s_ti[1][j]);
#pragma unroll
        for (int n = 0; n < TK; n++) {
            out[SC_OFF  + row * TK + n] = bv[n];
            out[IDX_OFF + row * TK + n] = (float)bi[n];
            s_idx[n] = bi[n];
        }
    }
    __syncthreads();

    // gather 4 concept rows (4 x 192 float4), 6 per thread
#pragma unroll
    for (int k = 0; k < 6; k++) {
        const int i = t + k * 128;
        const int n = i / 192, j = i % 192;
        const int cid = s_idx[n];
        const float4 val = ((const float4*)concepts)[(size_t)cid * 192 + j];
        ((float4*)(out + OC_OFF))[(size_t)(row * TK + n) * 192 + j] = val;
    }
}

extern "C" void kernel_launch(void* const* d_in, const int* in_sizes, int n_in,
                              void* d_out, int out_size) {
    const float* regs     = (const float*)d_in[0];
    const float* row_keys = (const float*)d_in[1];
    const float* col_keys = (const float*)d_in[2];
    const float* concepts = (const float*)d_in[3];
    const float* gamma    = (const float*)d_in[4];
    const float* beta     = (const float*)d_in[5];
    const float* Wq       = (const float*)d_in[6];
    const float* bq       = (const float*)d_in[7];
    const float* Wqc      = (const float*)d_in[8];
    const float* bqc      = (const float*)d_in[9];
    float* out = (float*)d_out;

    k1_ln_q<<<dim3(8, 32), 256>>>(regs, gamma, beta, Wq, bq);
    kb_scores_qp<<<320, 256>>>(row_keys, col_keys, Wqc, bqc, out);
    kc_topk_gather<<<256, 128>>>(concepts, out);
}